// round 8
// baseline (speedup 1.0000x reference)
#include <cuda_runtime.h>
#include <cuda_bf16.h>
#include <cstdint>

#define N_PTS 100000
#define D 128
#define NSM 148
#define SKPB 272               // bf16 row stride in bytes (136 bf16)
#define TILE_B 34816           // 128 * 272
#define BUF_SZ (2 * TILE_B)    // hi + lo image
#define TILES_A 782
#define TILES_BK 6250

// smem layout (shared by both kernels)
#define SB_WH   139264
#define SB_WL   (SB_WH + TILE_B)
#define SB_IDX  208896                  // 4 * 512
#define SB_XYZ  210944                  // 4 * 1536
#define SB_B2   217088                  // 512
#define SB_TOTB 217600
#define SB_TOTA 208896

__device__ float g_y[(size_t)N_PTS * D];

// ---------------- helpers ----------------
__device__ __forceinline__ uint32_t smem_u32(const void* p) {
    uint32_t a;
    asm("{ .reg .u64 t; cvta.to.shared.u64 t, %1; cvt.u32.u64 %0, t; }"
        : "=r"(a) : "l"(p));
    return a;
}
__device__ __forceinline__ uint32_t cvt_bf16x2(float hi, float lo) {
    uint32_t r;
    asm("cvt.rn.bf16x2.f32 %0, %1, %2;" : "=r"(r) : "f"(hi), "f"(lo));
    return r;
}
__device__ __forceinline__ void cp16(uint32_t dst, const void* src) {
    asm volatile("cp.async.cg.shared.global [%0], [%1], 16;"
                 :: "r"(dst), "l"(src) : "memory");
}
__device__ __forceinline__ void cp_commit() {
    asm volatile("cp.async.commit_group;" ::: "memory");
}
__device__ __forceinline__ void cp_wait0() {
    asm volatile("cp.async.wait_group 0;" ::: "memory");
}
__device__ __forceinline__ void cp_wait1() {
    asm volatile("cp.async.wait_group 1;" ::: "memory");
}
__device__ __forceinline__ void bar_prod() {       // producer-only barrier
    asm volatile("bar.sync 1, 256;" ::: "memory");
}
__device__ __forceinline__ void ldsm_x4(uint32_t addr, uint32_t* r) {
    asm volatile("ldmatrix.sync.aligned.m8n8.x4.shared.b16 {%0,%1,%2,%3}, [%4];"
                 : "=r"(r[0]), "=r"(r[1]), "=r"(r[2]), "=r"(r[3]) : "r"(addr));
}
__device__ __forceinline__ void ldsm_x2(uint32_t addr, uint32_t* r) {
    asm volatile("ldmatrix.sync.aligned.m8n8.x2.shared.b16 {%0,%1}, [%2];"
                 : "=r"(r[0]), "=r"(r[1]) : "r"(addr));
}
__device__ __forceinline__ void mma_bf16(float* d, const uint32_t* a, const uint32_t* b) {
    asm volatile(
        "mma.sync.aligned.m16n8k16.row.col.f32.bf16.bf16.f32 "
        "{%0,%1,%2,%3}, {%4,%5,%6,%7}, {%8,%9}, {%0,%1,%2,%3};"
        : "+f"(d[0]), "+f"(d[1]), "+f"(d[2]), "+f"(d[3])
        : "r"(a[0]), "r"(a[1]), "r"(a[2]), "r"(a[3]), "r"(b[0]), "r"(b[1]));
}
__device__ __forceinline__ void split4(float4 v, uint2& hi, uint2& lo) {
    uint32_t h01 = cvt_bf16x2(v.y, v.x);
    uint32_t h23 = cvt_bf16x2(v.w, v.z);
    float rx = v.x - __uint_as_float(h01 << 16);
    float ry = v.y - __uint_as_float(h01 & 0xffff0000u);
    float rz = v.z - __uint_as_float(h23 << 16);
    float rw = v.w - __uint_as_float(h23 & 0xffff0000u);
    hi = make_uint2(h01, h23);
    lo = make_uint2(cvt_bf16x2(ry, rx), cvt_bf16x2(rw, rz));
}
__device__ __forceinline__ float4 leaky4(float4 v) {
    v.x = v.x > 0.f ? v.x : 0.01f * v.x;
    v.y = v.y > 0.f ? v.y : 0.01f * v.y;
    v.z = v.z > 0.f ? v.z : 0.01f * v.z;
    v.w = v.w > 0.f ? v.w : 0.01f * v.w;
    return v;
}
__device__ __forceinline__ void build_w(char* smc, const float* W, int tid, int nthr) {
    for (int i = tid; i < 128 * 128; i += nthr) {
        int k = i >> 7, n = i & 127;
        float v = W[i];
        __nv_bfloat16 hb = __float2bfloat16(v);
        *(__nv_bfloat16*)(smc + SB_WH + n * SKPB + k * 2) = hb;
        *(__nv_bfloat16*)(smc + SB_WL + n * SKPB + k * 2) =
            __float2bfloat16(v - __bfloat162float(hb));
    }
}

// =====================================================================
// Kernel A (persistent, pipelined, 256 thr): y = x @ W1[0:128,:]
// (unchanged from R7 passing version)
// =====================================================================
__device__ __forceinline__ void mma_kstep64(uint32_t abuf, uint32_t aRowOff,
                                            uint32_t bRowW, int ks, float d[2][8][4]) {
    const uint32_t kb = ks * 32;
    uint32_t ah[2][4], al[2][4];
#pragma unroll
    for (int mt = 0; mt < 2; mt++) {
        uint32_t off = abuf + aRowOff + (uint32_t)mt * 16 * SKPB + kb;
        ldsm_x4(off, ah[mt]);
        ldsm_x4(off + TILE_B, al[mt]);
    }
    uint32_t bh[8][2], bl[8][2];
#pragma unroll
    for (int nt = 0; nt < 8; nt++) {
        uint32_t off = bRowW + (uint32_t)nt * 8 * SKPB + kb;
        ldsm_x2(off, bh[nt]);
        ldsm_x2(off + TILE_B, bl[nt]);
    }
#pragma unroll
    for (int mt = 0; mt < 2; mt++)
#pragma unroll
        for (int nt = 0; nt < 8; nt++) {
            mma_bf16(d[mt][nt], ah[mt], bh[nt]);
            mma_bf16(d[mt][nt], al[mt], bh[nt]);
            mma_bf16(d[mt][nt], ah[mt], bl[nt]);
        }
}

__global__ void __launch_bounds__(256, 1)
gemm1_kernel(const float* __restrict__ x, const float* __restrict__ W1) {
    extern __shared__ char smc[];
    const uint32_t sb = smem_u32(smc);
    const int tid = threadIdx.x, w = tid >> 5, lane = tid & 31;
    const int w16 = w * 16, c0 = lane * 4;
    const int m0 = (w & 3) * 32, n0 = (w >> 2) * 64;
    const uint32_t aRowOff = (uint32_t)(m0 + (lane & 15)) * SKPB + (lane >> 4) * 16;
    const uint32_t bRowW = sb + SB_WH + (uint32_t)(n0 + (lane & 7)) * SKPB +
                           ((lane >> 3) & 1) * 16;

    build_w(smc, W1, tid, 256);

    const int t0 = blockIdx.x;
    float4 xreg[16];
#pragma unroll
    for (int rr = 0; rr < 16; rr++) {
        int row = t0 * 128 + w16 + rr;
        xreg[rr] = *(const float4*)(x + (size_t)(row < N_PTS ? row : 0) * D + c0);
    }
#pragma unroll
    for (int rr = 0; rr < 16; rr++) {
        uint2 hi, lo; split4(xreg[rr], hi, lo);
        uint32_t off = (uint32_t)(w16 + rr) * SKPB + c0 * 2;
        *(uint2*)(smc + off) = hi;
        *(uint2*)(smc + TILE_B + off) = lo;
    }
    {
        int tn = t0 + NSM;
#pragma unroll
        for (int rr = 0; rr < 16; rr++) {
            int row = tn * 128 + w16 + rr;
            xreg[rr] = *(const float4*)(x + (size_t)(row < N_PTS ? row : 0) * D + c0);
        }
    }
    __syncthreads();

    int p = 0;
    for (int t = t0; t < TILES_A; t += NSM, p ^= 1) {
        const uint32_t abuf = sb + p * BUF_SZ;
        char* cb = smc + (p ^ 1) * BUF_SZ;
        const int t2 = t + 2 * NSM;

        float d[2][8][4];
#pragma unroll
        for (int mt = 0; mt < 2; mt++)
#pragma unroll
            for (int nt = 0; nt < 8; nt++)
#pragma unroll
                for (int j = 0; j < 4; j++) d[mt][nt][j] = 0.f;

#pragma unroll
        for (int ks = 0; ks < 8; ks++) {
            mma_kstep64(abuf, aRowOff, bRowW, ks, d);
            const int rr = 2 * ks;
#pragma unroll
            for (int q = 0; q < 2; q++) {
                uint2 hi, lo; split4(xreg[rr + q], hi, lo);
                uint32_t off = (uint32_t)(w16 + rr + q) * SKPB + c0 * 2;
                *(uint2*)(cb + off) = hi;
                *(uint2*)(cb + TILE_B + off) = lo;
                int row = t2 * 128 + w16 + rr + q;
                xreg[rr + q] =
                    *(const float4*)(x + (size_t)(row < N_PTS ? row : 0) * D + c0);
            }
        }

        const int g = lane >> 2, tt2 = 2 * (lane & 3);
        const int base = t * 128;
#pragma unroll
        for (int mt = 0; mt < 2; mt++) {
            int row0 = base + m0 + mt * 16 + g;
#pragma unroll
            for (int nt = 0; nt < 8; nt++) {
                int col = n0 + nt * 8 + tt2;
                if (row0 < N_PTS)
                    *(float2*)(g_y + (size_t)row0 * D + col) =
                        make_float2(d[mt][nt][0], d[mt][nt][1]);
                if (row0 + 8 < N_PTS)
                    *(float2*)(g_y + (size_t)(row0 + 8) * D + col) =
                        make_float2(d[mt][nt][2], d[mt][nt][3]);
            }
        }
        __syncthreads();
    }
}

// =====================================================================
// Kernel B: warp-specialized. Warps 0-7 consumers (m64xn32 HMMA),
// warps 8-15 producers (gather + layer-1 fuse + bf16 split + prefetch).
// =====================================================================
__device__ __forceinline__ void prefetch_ix_p(uint32_t sb, const int* idx,
                                              const float* xyz, int tile, int slot,
                                              int ptid) {
    if (tile >= TILES_BK) tile = TILES_BK - 1;
    if (ptid < 32)
        cp16(sb + SB_IDX + slot * 512 + ptid * 16, idx + (size_t)tile * 128 + ptid * 4);
    else if (ptid < 128)
        cp16(sb + SB_XYZ + slot * 1536 + (ptid - 32) * 16,
             xyz + (size_t)tile * 384 + (ptid - 32) * 4);
}

// producer: fill one A tile (16 rows) into cb from idx/xyz slot
__device__ __forceinline__ void produce_tile(const char* smc, char* cb, int slot,
                                             int pw, int lane, int c0,
                                             float4 wA, float4 wB, float4 wC,
                                             float4 bb) {
    const int* idxs = (const int*)(smc + SB_IDX + slot * 512);
    const float* xz = (const float*)(smc + SB_XYZ + slot * 1536);
    const char* gyc = (const char*)g_y;
    const uint32_t lane16 = lane * 16;
    const int rbase = pw * 16;

    float4 yv[8];
#pragma unroll
    for (int q = 0; q < 8; q++) {
        int id = idxs[rbase + q];
        yv[q] = *(const float4*)(gyc + (size_t)id * 512 + lane16);
    }
#pragma unroll
    for (int q = 0; q < 16; q++) {
        float4 v = yv[q & 7];
        if (q < 8) {   // refill slot with row q+8 (read-then-write)
            int id = idxs[rbase + q + 8];
            yv[q & 7] = *(const float4*)(gyc + (size_t)id * 512 + lane16);
        }
        int r = rbase + q;
        float px = xz[r * 3], py = xz[r * 3 + 1], pz = xz[r * 3 + 2];
        v.x += px * wA.x + py * wB.x + pz * wC.x + bb.x;
        v.y += px * wA.y + py * wB.y + pz * wC.y + bb.y;
        v.z += px * wA.z + py * wB.z + pz * wC.z + bb.z;
        v.w += px * wA.w + py * wB.w + pz * wC.w + bb.w;
        v = leaky4(v);
        uint2 hi, lo; split4(v, hi, lo);
        uint32_t off = (uint32_t)r * SKPB + c0 * 2;
        *(uint2*)(cb + off) = hi;
        *(uint2*)(cb + TILE_B + off) = lo;
    }
}

// consumer k-step: 12 LDSM + 48 HMMA for a warp's m64 x n32 slab
__device__ __forceinline__ void mma_kstep64x32(uint32_t abuf, uint32_t aBase,
                                               uint32_t bRow4, int ks,
                                               float d[4][4][4]) {
    const uint32_t kb = ks * 32;
    uint32_t bh[8], bl[8];
    ldsm_x4(bRow4 + kb, bh);
    ldsm_x4(bRow4 + 16 * SKPB + kb, bh + 4);
    ldsm_x4(bRow4 + TILE_B + kb, bl);
    ldsm_x4(bRow4 + TILE_B + 16 * SKPB + kb, bl + 4);
#pragma unroll
    for (int mt = 0; mt < 4; mt++) {
        uint32_t ah[4], al[4];
        uint32_t off = abuf + aBase + (uint32_t)mt * 16 * SKPB + kb;
        ldsm_x4(off, ah);
        ldsm_x4(off + TILE_B, al);
#pragma unroll
        for (int nt = 0; nt < 4; nt++) {
            const uint32_t* bph = &bh[(nt >> 1) * 4 + (nt & 1) * 2];
            const uint32_t* bpl = &bl[(nt >> 1) * 4 + (nt & 1) * 2];
            mma_bf16(d[mt][nt], ah, bph);
            mma_bf16(d[mt][nt], al, bph);
            mma_bf16(d[mt][nt], ah, bpl);
        }
    }
}

__global__ void __launch_bounds__(512, 1)
gemm2_pool_kernel(const int*   __restrict__ idx,
                  const float* __restrict__ xyz,
                  const float* __restrict__ W1,
                  const float* __restrict__ b1,
                  const float* __restrict__ W2,
                  const float* __restrict__ b2,
                  float* __restrict__ out) {
    extern __shared__ char smc[];
    const uint32_t sb = smem_u32(smc);
    const int tid = threadIdx.x, w = tid >> 5, lane = tid & 31;
    float* b2s = (float*)(smc + SB_B2);

    build_w(smc, W2, tid, 512);
    if (tid < 128) b2s[tid] = b2[tid];

    const int t0 = blockIdx.x;

    if (w >= 8) {
        // ---------------- producer prologue ----------------
        const int pw = w - 8, ptid = tid - 256, c0 = lane * 4;
        const float4 wA = *(const float4*)(W1 + 128 * 128 + c0);
        const float4 wB = *(const float4*)(W1 + 129 * 128 + c0);
        const float4 wC = *(const float4*)(W1 + 130 * 128 + c0);
        const float4 bb = *(const float4*)(b1 + c0);

        prefetch_ix_p(sb, idx, xyz, t0, 0, ptid);
        prefetch_ix_p(sb, idx, xyz, t0 + NSM, 1, ptid);
        prefetch_ix_p(sb, idx, xyz, t0 + 2 * NSM, 2, ptid);
        cp_commit();
        cp_wait0();
        bar_prod();
        produce_tile(smc, smc /*buf0*/, 0, pw, lane, c0, wA, wB, wC, bb);
        __syncthreads();

        // ---------------- producer loop ----------------
        int i = 0;
        for (int t = t0; t < TILES_BK; t += NSM, i++) {
            cp_wait1();            // slot (i+1) committed at iter i-2 is done
            bar_prod();            // publish to all producer threads
            int tn = t + NSM;
            if (tn < TILES_BK)
                produce_tile(smc, smc + ((i + 1) & 1) * BUF_SZ, (i + 1) & 3,
                             pw, lane, c0, wA, wB, wC, bb);
            prefetch_ix_p(sb, idx, xyz, t + 3 * NSM, (i + 3) & 3, ptid);
            cp_commit();
            __syncthreads();
        }
    } else {
        // ---------------- consumer ----------------
        const int m0 = (w & 1) * 64, n0 = (w >> 1) * 32;
        const uint32_t aBase = (uint32_t)(m0 + (lane & 15)) * SKPB + (lane >> 4) * 16;
        const uint32_t bRow4 = sb + SB_WH +
            (uint32_t)(n0 + (lane & 7) + ((lane >> 4) & 1) * 8) * SKPB +
            ((lane >> 3) & 1) * 16;
        __syncthreads();           // matches producer prologue sync

        int i = 0;
        for (int t = t0; t < TILES_BK; t += NSM, i++) {
            const uint32_t abuf = sb + (i & 1) * BUF_SZ;

            float d[4][4][4];
#pragma unroll
            for (int mt = 0; mt < 4; mt++)
#pragma unroll
                for (int nt = 0; nt < 4; nt++)
#pragma unroll
                    for (int j = 0; j < 4; j++) d[mt][nt][j] = 0.f;

#pragma unroll
            for (int ks = 0; ks < 8; ks++)
                mma_kstep64x32(abuf, aBase, bRow4, ks, d);

            // epilogue: maxpool over 8 rows, +b2, store
            const long rowbase = (long)t * 128;
            const int tt2 = 2 * (lane & 3);
#pragma unroll
            for (int mt = 0; mt < 4; mt++) {
                long p0 = (rowbase + m0 + mt * 16) >> 3;
                long p1 = p0 + 1;
#pragma unroll
                for (int nt = 0; nt < 4; nt++) {
                    float v0 = d[mt][nt][0], v1 = d[mt][nt][1];
                    float v2 = d[mt][nt][2], v3 = d[mt][nt][3];
#pragma unroll
                    for (int s = 4; s < 32; s <<= 1) {
                        v0 = fmaxf(v0, __shfl_xor_sync(0xffffffffu, v0, s));
                        v1 = fmaxf(v1, __shfl_xor_sync(0xffffffffu, v1, s));
                        v2 = fmaxf(v2, __shfl_xor_sync(0xffffffffu, v2, s));
                        v3 = fmaxf(v3, __shfl_xor_sync(0xffffffffu, v3, s));
                    }
                    if (lane < 4) {
                        int col = n0 + nt * 8 + tt2;
                        float bx = b2s[col], by = b2s[col + 1];
                        *(float2*)(out + (size_t)p0 * D + col) =
                            make_float2(v0 + bx, v1 + by);
                        *(float2*)(out + (size_t)p1 * D + col) =
                            make_float2(v2 + bx, v3 + by);
                    }
                }
            }
            __syncthreads();
        }
    }
}

// =====================================================================
extern "C" void kernel_launch(void* const* d_in, const int* in_sizes, int n_in,
                              void* d_out, int out_size) {
    const float* x   = (const float*)d_in[0];
    const int*   idx = (const int*)d_in[1];
    const float* xyz = (const float*)d_in[2];
    const float* W1  = (const float*)d_in[3];
    const float* b1  = (const float*)d_in[4];
    const float* W2  = (const float*)d_in[5];
    const float* b2  = (const float*)d_in[6];
    float* out = (float*)d_out;

    cudaFuncSetAttribute(gemm1_kernel,
                         cudaFuncAttributeMaxDynamicSharedMemorySize, SB_TOTA);
    cudaFuncSetAttribute(gemm2_pool_kernel,
                         cudaFuncAttributeMaxDynamicSharedMemorySize, SB_TOTB);

    gemm1_kernel<<<NSM, 256, SB_TOTA>>>(x, W1);
    gemm2_pool_kernel<<<NSM, 512, SB_TOTB>>>(idx, xyz, W1, b1, W2, b2, out);
}

// round 9
// speedup vs baseline: 1.2487x; 1.2487x over previous
#include <cuda_runtime.h>
#include <cuda_bf16.h>
#include <cuda_fp16.h>
#include <cstdint>

#define N_PTS 100000
#define D 128
#define NSM 148
#define SKPB 272               // 16b row stride in bytes (136 elems)
#define TILE_B 34816           // 128 * 272
#define BUF_SZ (2 * TILE_B)
#define TILES_A 782
#define TILES_BK 6250

// kernel A smem layout (bf16 split-3, unchanged)
#define SA_WH   139264
#define SA_WL   (SA_WH + TILE_B)
#define SA_TOT  208896

// kernel B smem layout (fp16 split-2)
#define B_WH    69632                  // after 2 single-image A buffers
#define B_WL    (B_WH + TILE_B)        // 104448
#define B_IDX   139264                 // 4 * 512
#define B_XYZ   141312                 // 4 * 1536
#define B_B2    147456                 // 512
#define B_TOT   147968

__device__ float g_y[(size_t)N_PTS * D];

// ---------------- helpers ----------------
__device__ __forceinline__ uint32_t smem_u32(const void* p) {
    uint32_t a;
    asm("{ .reg .u64 t; cvta.to.shared.u64 t, %1; cvt.u32.u64 %0, t; }"
        : "=r"(a) : "l"(p));
    return a;
}
__device__ __forceinline__ uint32_t cvt_bf16x2(float hi, float lo) {
    uint32_t r;
    asm("cvt.rn.bf16x2.f32 %0, %1, %2;" : "=r"(r) : "f"(hi), "f"(lo));
    return r;
}
__device__ __forceinline__ uint32_t cvt_f16x2(float hi, float lo) {
    uint32_t r;
    asm("cvt.rn.f16x2.f32 %0, %1, %2;" : "=r"(r) : "f"(hi), "f"(lo));
    return r;
}
__device__ __forceinline__ void cp16(uint32_t dst, const void* src) {
    asm volatile("cp.async.cg.shared.global [%0], [%1], 16;"
                 :: "r"(dst), "l"(src) : "memory");
}
__device__ __forceinline__ void cp_commit() {
    asm volatile("cp.async.commit_group;" ::: "memory");
}
__device__ __forceinline__ void cp_wait0() {
    asm volatile("cp.async.wait_group 0;" ::: "memory");
}
__device__ __forceinline__ void ldsm_x4(uint32_t addr, uint32_t* r) {
    asm volatile("ldmatrix.sync.aligned.m8n8.x4.shared.b16 {%0,%1,%2,%3}, [%4];"
                 : "=r"(r[0]), "=r"(r[1]), "=r"(r[2]), "=r"(r[3]) : "r"(addr));
}
__device__ __forceinline__ void ldsm_x2(uint32_t addr, uint32_t* r) {
    asm volatile("ldmatrix.sync.aligned.m8n8.x2.shared.b16 {%0,%1}, [%2];"
                 : "=r"(r[0]), "=r"(r[1]) : "r"(addr));
}
__device__ __forceinline__ void mma_bf16(float* d, const uint32_t* a, const uint32_t* b) {
    asm volatile(
        "mma.sync.aligned.m16n8k16.row.col.f32.bf16.bf16.f32 "
        "{%0,%1,%2,%3}, {%4,%5,%6,%7}, {%8,%9}, {%0,%1,%2,%3};"
        : "+f"(d[0]), "+f"(d[1]), "+f"(d[2]), "+f"(d[3])
        : "r"(a[0]), "r"(a[1]), "r"(a[2]), "r"(a[3]), "r"(b[0]), "r"(b[1]));
}
__device__ __forceinline__ void mma_f16(float* d, const uint32_t* a, const uint32_t* b) {
    asm volatile(
        "mma.sync.aligned.m16n8k16.row.col.f32.f16.f16.f32 "
        "{%0,%1,%2,%3}, {%4,%5,%6,%7}, {%8,%9}, {%0,%1,%2,%3};"
        : "+f"(d[0]), "+f"(d[1]), "+f"(d[2]), "+f"(d[3])
        : "r"(a[0]), "r"(a[1]), "r"(a[2]), "r"(a[3]), "r"(b[0]), "r"(b[1]));
}
__device__ __forceinline__ void split4(float4 v, uint2& hi, uint2& lo) {
    uint32_t h01 = cvt_bf16x2(v.y, v.x);
    uint32_t h23 = cvt_bf16x2(v.w, v.z);
    float rx = v.x - __uint_as_float(h01 << 16);
    float ry = v.y - __uint_as_float(h01 & 0xffff0000u);
    float rz = v.z - __uint_as_float(h23 << 16);
    float rw = v.w - __uint_as_float(h23 & 0xffff0000u);
    hi = make_uint2(h01, h23);
    lo = make_uint2(cvt_bf16x2(ry, rx), cvt_bf16x2(rw, rz));
}
__device__ __forceinline__ float4 leaky4(float4 v) {
    v.x = v.x > 0.f ? v.x : 0.01f * v.x;
    v.y = v.y > 0.f ? v.y : 0.01f * v.y;
    v.z = v.z > 0.f ? v.z : 0.01f * v.z;
    v.w = v.w > 0.f ? v.w : 0.01f * v.w;
    return v;
}

// =====================================================================
// Kernel A (persistent, pipelined, 256 thr, bf16 split-3) — unchanged
// =====================================================================
__device__ __forceinline__ void build_w_bf16(char* smc, const float* W, int tid) {
    for (int i = tid; i < 128 * 128; i += 256) {
        int k = i >> 7, n = i & 127;
        float v = W[i];
        __nv_bfloat16 hb = __float2bfloat16(v);
        *(__nv_bfloat16*)(smc + SA_WH + n * SKPB + k * 2) = hb;
        *(__nv_bfloat16*)(smc + SA_WL + n * SKPB + k * 2) =
            __float2bfloat16(v - __bfloat162float(hb));
    }
}

__device__ __forceinline__ void mma_kstep64(uint32_t abuf, uint32_t aRowOff,
                                            uint32_t bRowW, int ks, float d[2][8][4]) {
    const uint32_t kb = ks * 32;
    uint32_t ah[2][4], al[2][4];
#pragma unroll
    for (int mt = 0; mt < 2; mt++) {
        uint32_t off = abuf + aRowOff + (uint32_t)mt * 16 * SKPB + kb;
        ldsm_x4(off, ah[mt]);
        ldsm_x4(off + TILE_B, al[mt]);
    }
    uint32_t bh[8][2], bl[8][2];
#pragma unroll
    for (int nt = 0; nt < 8; nt++) {
        uint32_t off = bRowW + (uint32_t)nt * 8 * SKPB + kb;
        ldsm_x2(off, bh[nt]);
        ldsm_x2(off + TILE_B, bl[nt]);
    }
#pragma unroll
    for (int mt = 0; mt < 2; mt++)
#pragma unroll
        for (int nt = 0; nt < 8; nt++) {
            mma_bf16(d[mt][nt], ah[mt], bh[nt]);
            mma_bf16(d[mt][nt], al[mt], bh[nt]);
            mma_bf16(d[mt][nt], ah[mt], bl[nt]);
        }
}

__global__ void __launch_bounds__(256, 1)
gemm1_kernel(const float* __restrict__ x, const float* __restrict__ W1) {
    extern __shared__ char smc[];
    const uint32_t sb = smem_u32(smc);
    const int tid = threadIdx.x, w = tid >> 5, lane = tid & 31;
    const int w16 = w * 16, c0 = lane * 4;
    const int m0 = (w & 3) * 32, n0 = (w >> 2) * 64;
    const uint32_t aRowOff = (uint32_t)(m0 + (lane & 15)) * SKPB + (lane >> 4) * 16;
    const uint32_t bRowW = sb + SA_WH + (uint32_t)(n0 + (lane & 7)) * SKPB +
                           ((lane >> 3) & 1) * 16;

    build_w_bf16(smc, W1, tid);

    const int t0 = blockIdx.x;
    float4 xreg[16];
#pragma unroll
    for (int rr = 0; rr < 16; rr++) {
        int row = t0 * 128 + w16 + rr;
        xreg[rr] = *(const float4*)(x + (size_t)(row < N_PTS ? row : 0) * D + c0);
    }
#pragma unroll
    for (int rr = 0; rr < 16; rr++) {
        uint2 hi, lo; split4(xreg[rr], hi, lo);
        uint32_t off = (uint32_t)(w16 + rr) * SKPB + c0 * 2;
        *(uint2*)(smc + off) = hi;
        *(uint2*)(smc + TILE_B + off) = lo;
    }
    {
        int tn = t0 + NSM;
#pragma unroll
        for (int rr = 0; rr < 16; rr++) {
            int row = tn * 128 + w16 + rr;
            xreg[rr] = *(const float4*)(x + (size_t)(row < N_PTS ? row : 0) * D + c0);
        }
    }
    __syncthreads();

    int p = 0;
    for (int t = t0; t < TILES_A; t += NSM, p ^= 1) {
        const uint32_t abuf = sb + p * BUF_SZ;
        char* cb = smc + (p ^ 1) * BUF_SZ;
        const int t2 = t + 2 * NSM;

        float d[2][8][4];
#pragma unroll
        for (int mt = 0; mt < 2; mt++)
#pragma unroll
            for (int nt = 0; nt < 8; nt++)
#pragma unroll
                for (int j = 0; j < 4; j++) d[mt][nt][j] = 0.f;

#pragma unroll
        for (int ks = 0; ks < 8; ks++) {
            mma_kstep64(abuf, aRowOff, bRowW, ks, d);
            const int rr = 2 * ks;
#pragma unroll
            for (int q = 0; q < 2; q++) {
                uint2 hi, lo; split4(xreg[rr + q], hi, lo);
                uint32_t off = (uint32_t)(w16 + rr + q) * SKPB + c0 * 2;
                *(uint2*)(cb + off) = hi;
                *(uint2*)(cb + TILE_B + off) = lo;
                int row = t2 * 128 + w16 + rr + q;
                xreg[rr + q] =
                    *(const float4*)(x + (size_t)(row < N_PTS ? row : 0) * D + c0);
            }
        }

        const int g = lane >> 2, tt2 = 2 * (lane & 3);
        const int base = t * 128;
#pragma unroll
        for (int mt = 0; mt < 2; mt++) {
            int row0 = base + m0 + mt * 16 + g;
#pragma unroll
            for (int nt = 0; nt < 8; nt++) {
                int col = n0 + nt * 8 + tt2;
                if (row0 < N_PTS)
                    *(float2*)(g_y + (size_t)row0 * D + col) =
                        make_float2(d[mt][nt][0], d[mt][nt][1]);
                if (row0 + 8 < N_PTS)
                    *(float2*)(g_y + (size_t)(row0 + 8) * D + col) =
                        make_float2(d[mt][nt][2], d[mt][nt][3]);
            }
        }
        __syncthreads();
    }
}

// =====================================================================
// Kernel B (R7 structure, fp16 split-2): A single fp16, W2 = Wh+Wl fp16
//  D = A*Wh + A*Wl ; 16 warps m32xn32; convert/gather interleaved
// =====================================================================
__device__ __forceinline__ void build_w_f16(char* smc, const float* W, int tid) {
    for (int i = tid; i < 128 * 128; i += 512) {
        int k = i >> 7, n = i & 127;
        float v = W[i];
        __half hb = __float2half_rn(v);
        *(__half*)(smc + B_WH + n * SKPB + k * 2) = hb;
        *(__half*)(smc + B_WL + n * SKPB + k * 2) =
            __float2half_rn(v - __half2float(hb));
    }
}
__device__ __forceinline__ void prefetch_ix(uint32_t sb, const int* idx,
                                            const float* xyz, int tile, int slot,
                                            int tid) {
    if (tile >= TILES_BK) tile = TILES_BK - 1;
    if (tid < 32)
        cp16(sb + B_IDX + slot * 512 + tid * 16, idx + (size_t)tile * 128 + tid * 4);
    else if (tid < 128)
        cp16(sb + B_XYZ + slot * 1536 + (tid - 32) * 16,
             xyz + (size_t)tile * 384 + (tid - 32) * 4);
}

// one k-step: 6 LDSM + 16 HMMA for a warp's m32 x n32 slab
__device__ __forceinline__ void mma_kstep32(uint32_t abuf, uint32_t aRowOff,
                                            uint32_t bRow4, int ks, float d[2][4][4]) {
    const uint32_t kb = ks * 32;
    uint32_t a[2][4];
#pragma unroll
    for (int mt = 0; mt < 2; mt++)
        ldsm_x4(abuf + aRowOff + (uint32_t)mt * 16 * SKPB + kb, a[mt]);
    uint32_t bh[8], bl[8];
    ldsm_x4(bRow4 + kb, bh);
    ldsm_x4(bRow4 + 16 * SKPB + kb, bh + 4);
    ldsm_x4(bRow4 + TILE_B + kb, bl);
    ldsm_x4(bRow4 + TILE_B + 16 * SKPB + kb, bl + 4);
#pragma unroll
    for (int mt = 0; mt < 2; mt++)
#pragma unroll
        for (int nt = 0; nt < 4; nt++) {
            const uint32_t* bph = &bh[(nt >> 1) * 4 + (nt & 1) * 2];
            const uint32_t* bpl = &bl[(nt >> 1) * 4 + (nt & 1) * 2];
            mma_f16(d[mt][nt], a[mt], bph);
            mma_f16(d[mt][nt], a[mt], bpl);
        }
}

__global__ void __launch_bounds__(512, 1)
gemm2_pool_kernel(const int*   __restrict__ idx,
                  const float* __restrict__ xyz,
                  const float* __restrict__ W1,
                  const float* __restrict__ b1,
                  const float* __restrict__ W2,
                  const float* __restrict__ b2,
                  float* __restrict__ out) {
    extern __shared__ char smc[];
    const uint32_t sb = smem_u32(smc);
    const int tid = threadIdx.x, w = tid >> 5, lane = tid & 31;
    const int w8 = w * 8, c0 = lane * 4;
    const int m0 = (w & 3) * 32, n0 = (w >> 2) * 32;
    const uint32_t aRowOff = (uint32_t)(m0 + (lane & 15)) * SKPB + (lane >> 4) * 16;
    const uint32_t bRow4 = sb + B_WH +
        (uint32_t)(n0 + (lane & 7) + ((lane >> 4) & 1) * 8) * SKPB +
        ((lane >> 3) & 1) * 16;
    const char* gyc = (const char*)g_y;
    const uint32_t lane16 = lane * 16;
    float* b2s = (float*)(smc + B_B2);

    build_w_f16(smc, W2, tid);
    if (tid < 128) b2s[tid] = b2[tid];

    const float4 wA = *(const float4*)(W1 + 128 * 128 + c0);
    const float4 wB = *(const float4*)(W1 + 129 * 128 + c0);
    const float4 wC = *(const float4*)(W1 + 130 * 128 + c0);
    const float4 bb = *(const float4*)(b1 + c0);

    const int t0 = blockIdx.x;
    prefetch_ix(sb, idx, xyz, t0, 0, tid);
    prefetch_ix(sb, idx, xyz, t0 + NSM, 1, tid);
    prefetch_ix(sb, idx, xyz, t0 + 2 * NSM, 2, tid);
    cp_commit();
    cp_wait0();
    __syncthreads();

    // prologue: gather+convert tile t0 -> buf0 (8 rows per warp)
    {
        const int* idxs = (const int*)(smc + B_IDX);
        const float* xz = (const float*)(smc + B_XYZ);
#pragma unroll
        for (int rr = 0; rr < 8; rr++) {
            int r = w8 + rr;
            int id = idxs[r];
            float4 v = *(const float4*)(gyc + (size_t)id * 512 + lane16);
            float px = xz[r * 3], py = xz[r * 3 + 1], pz = xz[r * 3 + 2];
            v.x += px * wA.x + py * wB.x + pz * wC.x + bb.x;
            v.y += px * wA.y + py * wB.y + pz * wC.y + bb.y;
            v.z += px * wA.z + py * wB.z + pz * wC.z + bb.z;
            v.w += px * wA.w + py * wB.w + pz * wC.w + bb.w;
            v = leaky4(v);
            uint32_t off = (uint32_t)r * SKPB + c0 * 2;
            *(uint2*)(smc + off) =
                make_uint2(cvt_f16x2(v.y, v.x), cvt_f16x2(v.w, v.z));
        }
    }
    __syncthreads();

    float4 yring[4];
    int p = 0, i = 0;
    for (int t = t0; t < TILES_BK; t += NSM, i++, p ^= 1) {
        const int* idx1 = (const int*)(smc + B_IDX + ((i + 1) & 3) * 512);
        const float* xz1 = (const float*)(smc + B_XYZ + ((i + 1) & 3) * 1536);
        const uint32_t abuf = sb + p * TILE_B;
        char* cb = smc + (p ^ 1) * TILE_B;

        float d[2][4][4];
#pragma unroll
        for (int mt = 0; mt < 2; mt++)
#pragma unroll
            for (int nt = 0; nt < 4; nt++)
#pragma unroll
                for (int j = 0; j < 4; j++) d[mt][nt][j] = 0.f;

#pragma unroll
        for (int ks = 0; ks < 8; ks++) {
            mma_kstep32(abuf, aRowOff, bRow4, ks, d);
            // convert rows gathered 2 steps ago BEFORE regathering same slots
            if (ks >= 2 && ks < 6) {
                const int rr = 2 * (ks - 2);
#pragma unroll
                for (int q = 0; q < 2; q++) {
                    int r = w8 + rr + q;
                    float px = xz1[r * 3], py = xz1[r * 3 + 1], pz = xz1[r * 3 + 2];
                    float4 v = yring[(rr + q) & 3];
                    v.x += px * wA.x + py * wB.x + pz * wC.x + bb.x;
                    v.y += px * wA.y + py * wB.y + pz * wC.y + bb.y;
                    v.z += px * wA.z + py * wB.z + pz * wC.z + bb.z;
                    v.w += px * wA.w + py * wB.w + pz * wC.w + bb.w;
                    v = leaky4(v);
                    uint32_t off = (uint32_t)r * SKPB + c0 * 2;
                    *(uint2*)(cb + off) =
                        make_uint2(cvt_f16x2(v.y, v.x), cvt_f16x2(v.w, v.z));
                }
            }
            if (ks < 4) {
                const int rr = 2 * ks;
#pragma unroll
                for (int q = 0; q < 2; q++) {
                    int id = idx1[w8 + rr + q];
                    yring[(rr + q) & 3] =
                        *(const float4*)(gyc + (size_t)id * 512 + lane16);
                }
            }
        }

        cp_wait0();
        prefetch_ix(sb, idx, xyz, t + 3 * NSM, (i + 3) & 3, tid);
        cp_commit();

        // epilogue: maxpool over 8 rows, +b2, store
        const long rowbase = (long)t * 128;
        const int tt2 = 2 * (lane & 3);
#pragma unroll
        for (int mt = 0; mt < 2; mt++) {
            long p0 = (rowbase + m0 + mt * 16) >> 3;
            long p1 = p0 + 1;
#pragma unroll
            for (int nt = 0; nt < 4; nt++) {
                float v0 = d[mt][nt][0], v1 = d[mt][nt][1];
                float v2 = d[mt][nt][2], v3 = d[mt][nt][3];
#pragma unroll
                for (int s = 4; s < 32; s <<= 1) {
                    v0 = fmaxf(v0, __shfl_xor_sync(0xffffffffu, v0, s));
                    v1 = fmaxf(v1, __shfl_xor_sync(0xffffffffu, v1, s));
                    v2 = fmaxf(v2, __shfl_xor_sync(0xffffffffu, v2, s));
                    v3 = fmaxf(v3, __shfl_xor_sync(0xffffffffu, v3, s));
                }
                if (lane < 4) {
                    int col = n0 + nt * 8 + tt2;
                    float bx = b2s[col], by = b2s[col + 1];
                    *(float2*)(out + (size_t)p0 * D + col) = make_float2(v0 + bx, v1 + by);
                    *(float2*)(out + (size_t)p1 * D + col) = make_float2(v2 + bx, v3 + by);
                }
            }
        }
        __syncthreads();
    }
}

// =====================================================================
extern "C" void kernel_launch(void* const* d_in, const int* in_sizes, int n_in,
                              void* d_out, int out_size) {
    const float* x   = (const float*)d_in[0];
    const int*   idx = (const int*)d_in[1];
    const float* xyz = (const float*)d_in[2];
    const float* W1  = (const float*)d_in[3];
    const float* b1  = (const float*)d_in[4];
    const float* W2  = (const float*)d_in[5];
    const float* b2  = (const float*)d_in[6];
    float* out = (float*)d_out;

    cudaFuncSetAttribute(gemm1_kernel,
                         cudaFuncAttributeMaxDynamicSharedMemorySize, SA_TOT);
    cudaFuncSetAttribute(gemm2_pool_kernel,
                         cudaFuncAttributeMaxDynamicSharedMemorySize, B_TOT);

    gemm1_kernel<<<NSM, 256, SA_TOT>>>(x, W1);
    gemm2_pool_kernel<<<NSM, 512, B_TOT>>>(idx, xyz, W1, b1, W2, b2, out);
}

// round 10
// speedup vs baseline: 1.5115x; 1.2105x over previous
#include <cuda_runtime.h>
#include <cuda_bf16.h>
#include <cuda_fp16.h>
#include <cstdint>

#define N_PTS 100000
#define D 128
#define NSM 148
#define SKPB 272               // 16b row stride in bytes (136 elems)
#define TILE_B 34816           // 128 * 272
#define BUF_SZ (2 * TILE_B)
#define TILES_A 782
#define TILES_BK 6250

// kernel A smem layout (bf16 split-3, unchanged)
#define SA_WH   139264
#define SA_WL   (SA_WH + TILE_B)
#define SA_TOT  208896

// kernel B smem layout (plain fp16)
#define B_WH    69632                  // after 2 single-image A buffers
#define B_IDX   104448                 // 4 * 512
#define B_XYZ   106496                 // 4 * 1536
#define B_B2    112640                 // 512
#define B_TOT   113152

__device__ float g_y[(size_t)N_PTS * D];

// ---------------- helpers ----------------
__device__ __forceinline__ uint32_t smem_u32(const void* p) {
    uint32_t a;
    asm("{ .reg .u64 t; cvta.to.shared.u64 t, %1; cvt.u32.u64 %0, t; }"
        : "=r"(a) : "l"(p));
    return a;
}
__device__ __forceinline__ uint32_t cvt_bf16x2(float hi, float lo) {
    uint32_t r;
    asm("cvt.rn.bf16x2.f32 %0, %1, %2;" : "=r"(r) : "f"(hi), "f"(lo));
    return r;
}
__device__ __forceinline__ uint32_t cvt_f16x2(float hi, float lo) {
    uint32_t r;
    asm("cvt.rn.f16x2.f32 %0, %1, %2;" : "=r"(r) : "f"(hi), "f"(lo));
    return r;
}
__device__ __forceinline__ void cp16(uint32_t dst, const void* src) {
    asm volatile("cp.async.cg.shared.global [%0], [%1], 16;"
                 :: "r"(dst), "l"(src) : "memory");
}
__device__ __forceinline__ void cp_commit() {
    asm volatile("cp.async.commit_group;" ::: "memory");
}
__device__ __forceinline__ void cp_wait0() {
    asm volatile("cp.async.wait_group 0;" ::: "memory");
}
__device__ __forceinline__ void ldsm_x4(uint32_t addr, uint32_t* r) {
    asm volatile("ldmatrix.sync.aligned.m8n8.x4.shared.b16 {%0,%1,%2,%3}, [%4];"
                 : "=r"(r[0]), "=r"(r[1]), "=r"(r[2]), "=r"(r[3]) : "r"(addr));
}
__device__ __forceinline__ void ldsm_x2(uint32_t addr, uint32_t* r) {
    asm volatile("ldmatrix.sync.aligned.m8n8.x2.shared.b16 {%0,%1}, [%2];"
                 : "=r"(r[0]), "=r"(r[1]) : "r"(addr));
}
__device__ __forceinline__ void mma_bf16(float* d, const uint32_t* a, const uint32_t* b) {
    asm volatile(
        "mma.sync.aligned.m16n8k16.row.col.f32.bf16.bf16.f32 "
        "{%0,%1,%2,%3}, {%4,%5,%6,%7}, {%8,%9}, {%0,%1,%2,%3};"
        : "+f"(d[0]), "+f"(d[1]), "+f"(d[2]), "+f"(d[3])
        : "r"(a[0]), "r"(a[1]), "r"(a[2]), "r"(a[3]), "r"(b[0]), "r"(b[1]));
}
__device__ __forceinline__ void mma_f16(float* d, const uint32_t* a, const uint32_t* b) {
    asm volatile(
        "mma.sync.aligned.m16n8k16.row.col.f32.f16.f16.f32 "
        "{%0,%1,%2,%3}, {%4,%5,%6,%7}, {%8,%9}, {%0,%1,%2,%3};"
        : "+f"(d[0]), "+f"(d[1]), "+f"(d[2]), "+f"(d[3])
        : "r"(a[0]), "r"(a[1]), "r"(a[2]), "r"(a[3]), "r"(b[0]), "r"(b[1]));
}
__device__ __forceinline__ void split4(float4 v, uint2& hi, uint2& lo) {
    uint32_t h01 = cvt_bf16x2(v.y, v.x);
    uint32_t h23 = cvt_bf16x2(v.w, v.z);
    float rx = v.x - __uint_as_float(h01 << 16);
    float ry = v.y - __uint_as_float(h01 & 0xffff0000u);
    float rz = v.z - __uint_as_float(h23 << 16);
    float rw = v.w - __uint_as_float(h23 & 0xffff0000u);
    hi = make_uint2(h01, h23);
    lo = make_uint2(cvt_bf16x2(ry, rx), cvt_bf16x2(rw, rz));
}
__device__ __forceinline__ float4 leaky4(float4 v) {
    v.x = v.x > 0.f ? v.x : 0.01f * v.x;
    v.y = v.y > 0.f ? v.y : 0.01f * v.y;
    v.z = v.z > 0.f ? v.z : 0.01f * v.z;
    v.w = v.w > 0.f ? v.w : 0.01f * v.w;
    return v;
}

// =====================================================================
// Kernel A (persistent, pipelined, 256 thr, bf16 split-3) — unchanged
// =====================================================================
__device__ __forceinline__ void build_w_bf16(char* smc, const float* W, int tid) {
    for (int i = tid; i < 128 * 128; i += 256) {
        int k = i >> 7, n = i & 127;
        float v = W[i];
        __nv_bfloat16 hb = __float2bfloat16(v);
        *(__nv_bfloat16*)(smc + SA_WH + n * SKPB + k * 2) = hb;
        *(__nv_bfloat16*)(smc + SA_WL + n * SKPB + k * 2) =
            __float2bfloat16(v - __bfloat162float(hb));
    }
}

__device__ __forceinline__ void mma_kstep64(uint32_t abuf, uint32_t aRowOff,
                                            uint32_t bRowW, int ks, float d[2][8][4]) {
    const uint32_t kb = ks * 32;
    uint32_t ah[2][4], al[2][4];
#pragma unroll
    for (int mt = 0; mt < 2; mt++) {
        uint32_t off = abuf + aRowOff + (uint32_t)mt * 16 * SKPB + kb;
        ldsm_x4(off, ah[mt]);
        ldsm_x4(off + TILE_B, al[mt]);
    }
    uint32_t bh[8][2], bl[8][2];
#pragma unroll
    for (int nt = 0; nt < 8; nt++) {
        uint32_t off = bRowW + (uint32_t)nt * 8 * SKPB + kb;
        ldsm_x2(off, bh[nt]);
        ldsm_x2(off + TILE_B, bl[nt]);
    }
#pragma unroll
    for (int mt = 0; mt < 2; mt++)
#pragma unroll
        for (int nt = 0; nt < 8; nt++) {
            mma_bf16(d[mt][nt], ah[mt], bh[nt]);
            mma_bf16(d[mt][nt], al[mt], bh[nt]);
            mma_bf16(d[mt][nt], ah[mt], bl[nt]);
        }
}

__global__ void __launch_bounds__(256, 1)
gemm1_kernel(const float* __restrict__ x, const float* __restrict__ W1) {
    extern __shared__ char smc[];
    const uint32_t sb = smem_u32(smc);
    const int tid = threadIdx.x, w = tid >> 5, lane = tid & 31;
    const int w16 = w * 16, c0 = lane * 4;
    const int m0 = (w & 3) * 32, n0 = (w >> 2) * 64;
    const uint32_t aRowOff = (uint32_t)(m0 + (lane & 15)) * SKPB + (lane >> 4) * 16;
    const uint32_t bRowW = sb + SA_WH + (uint32_t)(n0 + (lane & 7)) * SKPB +
                           ((lane >> 3) & 1) * 16;

    build_w_bf16(smc, W1, tid);

    const int t0 = blockIdx.x;
    float4 xreg[16];
#pragma unroll
    for (int rr = 0; rr < 16; rr++) {
        int row = t0 * 128 + w16 + rr;
        xreg[rr] = *(const float4*)(x + (size_t)(row < N_PTS ? row : 0) * D + c0);
    }
#pragma unroll
    for (int rr = 0; rr < 16; rr++) {
        uint2 hi, lo; split4(xreg[rr], hi, lo);
        uint32_t off = (uint32_t)(w16 + rr) * SKPB + c0 * 2;
        *(uint2*)(smc + off) = hi;
        *(uint2*)(smc + TILE_B + off) = lo;
    }
    {
        int tn = t0 + NSM;
#pragma unroll
        for (int rr = 0; rr < 16; rr++) {
            int row = tn * 128 + w16 + rr;
            xreg[rr] = *(const float4*)(x + (size_t)(row < N_PTS ? row : 0) * D + c0);
        }
    }
    __syncthreads();

    int p = 0;
    for (int t = t0; t < TILES_A; t += NSM, p ^= 1) {
        const uint32_t abuf = sb + p * BUF_SZ;
        char* cb = smc + (p ^ 1) * BUF_SZ;
        const int t2 = t + 2 * NSM;

        float d[2][8][4];
#pragma unroll
        for (int mt = 0; mt < 2; mt++)
#pragma unroll
            for (int nt = 0; nt < 8; nt++)
#pragma unroll
                for (int j = 0; j < 4; j++) d[mt][nt][j] = 0.f;

#pragma unroll
        for (int ks = 0; ks < 8; ks++) {
            mma_kstep64(abuf, aRowOff, bRowW, ks, d);
            const int rr = 2 * ks;
#pragma unroll
            for (int q = 0; q < 2; q++) {
                uint2 hi, lo; split4(xreg[rr + q], hi, lo);
                uint32_t off = (uint32_t)(w16 + rr + q) * SKPB + c0 * 2;
                *(uint2*)(cb + off) = hi;
                *(uint2*)(cb + TILE_B + off) = lo;
                int row = t2 * 128 + w16 + rr + q;
                xreg[rr + q] =
                    *(const float4*)(x + (size_t)(row < N_PTS ? row : 0) * D + c0);
            }
        }

        const int g = lane >> 2, tt2 = 2 * (lane & 3);
        const int base = t * 128;
#pragma unroll
        for (int mt = 0; mt < 2; mt++) {
            int row0 = base + m0 + mt * 16 + g;
#pragma unroll
            for (int nt = 0; nt < 8; nt++) {
                int col = n0 + nt * 8 + tt2;
                if (row0 < N_PTS)
                    *(float2*)(g_y + (size_t)row0 * D + col) =
                        make_float2(d[mt][nt][0], d[mt][nt][1]);
                if (row0 + 8 < N_PTS)
                    *(float2*)(g_y + (size_t)(row0 + 8) * D + col) =
                        make_float2(d[mt][nt][2], d[mt][nt][3]);
            }
        }
        __syncthreads();
    }
}

// =====================================================================
// Kernel B (R7 structure, plain fp16): A fp16, W2 fp16 single image
//  D = A*W ; 16 warps m32xn32; convert/gather interleaved
// =====================================================================
__device__ __forceinline__ void build_w_f16(char* smc, const float* W, int tid) {
    for (int i = tid; i < 128 * 128; i += 512) {
        int k = i >> 7, n = i & 127;
        *(__half*)(smc + B_WH + n * SKPB + k * 2) = __float2half_rn(W[i]);
    }
}
__device__ __forceinline__ void prefetch_ix(uint32_t sb, const int* idx,
                                            const float* xyz, int tile, int slot,
                                            int tid) {
    if (tile >= TILES_BK) tile = TILES_BK - 1;
    if (tid < 32)
        cp16(sb + B_IDX + slot * 512 + tid * 16, idx + (size_t)tile * 128 + tid * 4);
    else if (tid < 128)
        cp16(sb + B_XYZ + slot * 1536 + (tid - 32) * 16,
             xyz + (size_t)tile * 384 + (tid - 32) * 4);
}

// one k-step: 4 LDSM + 8 HMMA for a warp's m32 x n32 slab
__device__ __forceinline__ void mma_kstep32(uint32_t abuf, uint32_t aRowOff,
                                            uint32_t bRow4, int ks, float d[2][4][4]) {
    const uint32_t kb = ks * 32;
    uint32_t a[2][4];
#pragma unroll
    for (int mt = 0; mt < 2; mt++)
        ldsm_x4(abuf + aRowOff + (uint32_t)mt * 16 * SKPB + kb, a[mt]);
    uint32_t b[8];
    ldsm_x4(bRow4 + kb, b);
    ldsm_x4(bRow4 + 16 * SKPB + kb, b + 4);
#pragma unroll
    for (int mt = 0; mt < 2; mt++)
#pragma unroll
        for (int nt = 0; nt < 4; nt++)
            mma_f16(d[mt][nt], a[mt], &b[(nt >> 1) * 4 + (nt & 1) * 2]);
}

__global__ void __launch_bounds__(512, 1)
gemm2_pool_kernel(const int*   __restrict__ idx,
                  const float* __restrict__ xyz,
                  const float* __restrict__ W1,
                  const float* __restrict__ b1,
                  const float* __restrict__ W2,
                  const float* __restrict__ b2,
                  float* __restrict__ out) {
    extern __shared__ char smc[];
    const uint32_t sb = smem_u32(smc);
    const int tid = threadIdx.x, w = tid >> 5, lane = tid & 31;
    const int w8 = w * 8, c0 = lane * 4;
    const int m0 = (w & 3) * 32, n0 = (w >> 2) * 32;
    const uint32_t aRowOff = (uint32_t)(m0 + (lane & 15)) * SKPB + (lane >> 4) * 16;
    const uint32_t bRow4 = sb + B_WH +
        (uint32_t)(n0 + (lane & 7) + ((lane >> 4) & 1) * 8) * SKPB +
        ((lane >> 3) & 1) * 16;
    const char* gyc = (const char*)g_y;
    const uint32_t lane16 = lane * 16;
    float* b2s = (float*)(smc + B_B2);

    build_w_f16(smc, W2, tid);
    if (tid < 128) b2s[tid] = b2[tid];

    const float4 wA = *(const float4*)(W1 + 128 * 128 + c0);
    const float4 wB = *(const float4*)(W1 + 129 * 128 + c0);
    const float4 wC = *(const float4*)(W1 + 130 * 128 + c0);
    const float4 bb = *(const float4*)(b1 + c0);

    const int t0 = blockIdx.x;
    prefetch_ix(sb, idx, xyz, t0, 0, tid);
    prefetch_ix(sb, idx, xyz, t0 + NSM, 1, tid);
    prefetch_ix(sb, idx, xyz, t0 + 2 * NSM, 2, tid);
    cp_commit();
    cp_wait0();
    __syncthreads();

    // prologue: gather+convert tile t0 -> buf0 (8 rows per warp)
    {
        const int* idxs = (const int*)(smc + B_IDX);
        const float* xz = (const float*)(smc + B_XYZ);
#pragma unroll
        for (int rr = 0; rr < 8; rr++) {
            int r = w8 + rr;
            int id = idxs[r];
            float4 v = *(const float4*)(gyc + (size_t)id * 512 + lane16);
            float px = xz[r * 3], py = xz[r * 3 + 1], pz = xz[r * 3 + 2];
            v.x += px * wA.x + py * wB.x + pz * wC.x + bb.x;
            v.y += px * wA.y + py * wB.y + pz * wC.y + bb.y;
            v.z += px * wA.z + py * wB.z + pz * wC.z + bb.z;
            v.w += px * wA.w + py * wB.w + pz * wC.w + bb.w;
            v = leaky4(v);
            uint32_t off = (uint32_t)r * SKPB + c0 * 2;
            *(uint2*)(smc + off) =
                make_uint2(cvt_f16x2(v.y, v.x), cvt_f16x2(v.w, v.z));
        }
    }
    __syncthreads();

    float4 yring[4];
    int p = 0, i = 0;
    for (int t = t0; t < TILES_BK; t += NSM, i++, p ^= 1) {
        const int* idx1 = (const int*)(smc + B_IDX + ((i + 1) & 3) * 512);
        const float* xz1 = (const float*)(smc + B_XYZ + ((i + 1) & 3) * 1536);
        const uint32_t abuf = sb + p * TILE_B;
        char* cb = smc + (p ^ 1) * TILE_B;

        float d[2][4][4];
#pragma unroll
        for (int mt = 0; mt < 2; mt++)
#pragma unroll
            for (int nt = 0; nt < 4; nt++)
#pragma unroll
                for (int j = 0; j < 4; j++) d[mt][nt][j] = 0.f;

#pragma unroll
        for (int ks = 0; ks < 8; ks++) {
            mma_kstep32(abuf, aRowOff, bRow4, ks, d);
            // convert rows gathered 2 steps ago BEFORE regathering same slots
            if (ks >= 2 && ks < 6) {
                const int rr = 2 * (ks - 2);
#pragma unroll
                for (int q = 0; q < 2; q++) {
                    int r = w8 + rr + q;
                    float px = xz1[r * 3], py = xz1[r * 3 + 1], pz = xz1[r * 3 + 2];
                    float4 v = yring[(rr + q) & 3];
                    v.x += px * wA.x + py * wB.x + pz * wC.x + bb.x;
                    v.y += px * wA.y + py * wB.y + pz * wC.y + bb.y;
                    v.z += px * wA.z + py * wB.z + pz * wC.z + bb.z;
                    v.w += px * wA.w + py * wB.w + pz * wC.w + bb.w;
                    v = leaky4(v);
                    uint32_t off = (uint32_t)r * SKPB + c0 * 2;
                    *(uint2*)(cb + off) =
                        make_uint2(cvt_f16x2(v.y, v.x), cvt_f16x2(v.w, v.z));
                }
            }
            if (ks < 4) {
                const int rr = 2 * ks;
#pragma unroll
                for (int q = 0; q < 2; q++) {
                    int id = idx1[w8 + rr + q];
                    yring[(rr + q) & 3] =
                        *(const float4*)(gyc + (size_t)id * 512 + lane16);
                }
            }
        }

        cp_wait0();
        prefetch_ix(sb, idx, xyz, t + 3 * NSM, (i + 3) & 3, tid);
        cp_commit();

        // epilogue: maxpool over 8 rows, +b2, store
        const long rowbase = (long)t * 128;
        const int tt2 = 2 * (lane & 3);
#pragma unroll
        for (int mt = 0; mt < 2; mt++) {
            long p0 = (rowbase + m0 + mt * 16) >> 3;
            long p1 = p0 + 1;
#pragma unroll
            for (int nt = 0; nt < 4; nt++) {
                float v0 = d[mt][nt][0], v1 = d[mt][nt][1];
                float v2 = d[mt][nt][2], v3 = d[mt][nt][3];
#pragma unroll
                for (int s = 4; s < 32; s <<= 1) {
                    v0 = fmaxf(v0, __shfl_xor_sync(0xffffffffu, v0, s));
                    v1 = fmaxf(v1, __shfl_xor_sync(0xffffffffu, v1, s));
                    v2 = fmaxf(v2, __shfl_xor_sync(0xffffffffu, v2, s));
                    v3 = fmaxf(v3, __shfl_xor_sync(0xffffffffu, v3, s));
                }
                if (lane < 4) {
                    int col = n0 + nt * 8 + tt2;
                    float bx = b2s[col], by = b2s[col + 1];
                    *(float2*)(out + (size_t)p0 * D + col) = make_float2(v0 + bx, v1 + by);
                    *(float2*)(out + (size_t)p1 * D + col) = make_float2(v2 + bx, v3 + by);
                }
            }
        }
        __syncthreads();
    }
}

// =====================================================================
extern "C" void kernel_launch(void* const* d_in, const int* in_sizes, int n_in,
                              void* d_out, int out_size) {
    const float* x   = (const float*)d_in[0];
    const int*   idx = (const int*)d_in[1];
    const float* xyz = (const float*)d_in[2];
    const float* W1  = (const float*)d_in[3];
    const float* b1  = (const float*)d_in[4];
    const float* W2  = (const float*)d_in[5];
    const float* b2  = (const float*)d_in[6];
    float* out = (float*)d_out;

    cudaFuncSetAttribute(gemm1_kernel,
                         cudaFuncAttributeMaxDynamicSharedMemorySize, SA_TOT);
    cudaFuncSetAttribute(gemm2_pool_kernel,
                         cudaFuncAttributeMaxDynamicSharedMemorySize, B_TOT);

    gemm1_kernel<<<NSM, 256, SA_TOT>>>(x, W1);
    gemm2_pool_kernel<<<NSM, 512, B_TOT>>>(idx, xyz, W1, b1, W2, b2, out);
}